// round 16
// baseline (speedup 1.0000x reference)
#include <cuda_runtime.h>
#include <cstddef>
#include <cstdint>

#define NN 100000
#define DD 128
#define FF 64
#define SS 16
#define NPB 32              // nodes per block (divides 100000)
#define NPT 16              // nodes per thread (GEMM phase, 256 threads = 2 halves)
#define WPAD 132            // padded smem row stride (528B): LDS.128 phases conflict-free
#define FPAD 68             // padded row stride for w_feat (272B), same mod-32 property

// Scratch embeddings (allocation-free rule: __device__ globals)
__device__ float g_x0[(size_t)NN * DD];
__device__ float g_x1[(size_t)NN * DD];

// Packed dual-fp32 FMA / ADD (PTX-only forms on sm_10x)
__device__ __forceinline__ void ffma2(unsigned long long& acc,
                                      unsigned long long a,
                                      unsigned long long b)
{
    asm("fma.rn.f32x2 %0, %1, %2, %0;" : "+l"(acc) : "l"(a), "l"(b));
}
__device__ __forceinline__ void fadd2(unsigned long long& a, unsigned long long b)
{
    asm("add.rn.f32x2 %0, %0, %1;" : "+l"(a) : "l"(b));
}
__device__ __forceinline__ float2 up2(unsigned long long v)
{
    float2 f;
    asm("mov.b64 {%0, %1}, %2;" : "=f"(f.x), "=f"(f.y) : "l"(v));
    return f;
}
__device__ __forceinline__ float pair_hsum(unsigned long long v)
{
    float2 f = up2(v);
    return f.x + f.y;
}
// 16B non-coherent global load (LDG.E.128.CONSTANT) reinterpreted as two u64 lanes
__device__ __forceinline__ ulonglong2 ldg128(const float* p)
{
    float4 v = __ldg((const float4*)p);
    ulonglong2 r;
    asm("mov.b64 %0, {%2, %3}; mov.b64 %1, {%4, %5};"
        : "=l"(r.x), "=l"(r.y) : "f"(v.x), "f"(v.y), "f"(v.z), "f"(v.w));
    return r;
}

// ---------------------------------------------------------------------------
// Kernel 1: x0 = feat @ w_feat^T      feat:[N,64], w_feat:[128,64]
// 256 threads: tid&127 = output dim, tid>>7 = node half (16 nodes each)
// ---------------------------------------------------------------------------
__global__ __launch_bounds__(256) void feat_kernel(
    const float* __restrict__ feat,
    const float* __restrict__ wf,
    float* __restrict__ xout)
{
    __shared__ float ws[DD * FPAD];
    __shared__ float fs[NPB * FF];

    const int tid  = threadIdx.x;     // 0..255
    const int d    = tid & 127;
    const int half = tid >> 7;
    const int base = blockIdx.x * NPB;

    // stage w_feat (float4, padded rows; 272B row stride keeps 16B alignment)
    for (int q = tid; q < DD * FF / 4; q += 256) {
        float4 v = __ldg(((const float4*)wf) + q);
        int dd = q >> 4, f = (q & 15) << 2;
        *(float4*)&ws[dd * FPAD + f] = v;
    }
    // stage features (float4): 512 quads
    for (int q = tid; q < NPB * FF / 4; q += 256)
        ((float4*)fs)[q] = __ldg(((const float4*)(feat + (size_t)base * FF)) + q);
    __syncthreads();

    unsigned long long acc2[NPT];
#pragma unroll
    for (int i = 0; i < NPT; i++) acc2[i] = 0ull;

    const float* fsh = fs + half * NPT * FF;
    const ulonglong2* wrow = (const ulonglong2*)&ws[d * FPAD];
#pragma unroll
    for (int f4 = 0; f4 < FF / 4; f4++) {
        ulonglong2 wv = wrow[f4];                                  // LDS.128, conflict-free
#pragma unroll
        for (int i = 0; i < NPT; i++) {
            ulonglong2 av = *(const ulonglong2*)&fsh[i * FF + 4 * f4];  // LDS.128 broadcast
            ffma2(acc2[i], wv.x, av.x);
            ffma2(acc2[i], wv.y, av.y);
        }
    }
#pragma unroll
    for (int i = 0; i < NPT; i++)
        xout[(size_t)(base + half * NPT + i) * DD + d] = pair_hsum(acc2[i]);
}

// ---------------------------------------------------------------------------
// Kernel 2: one GraphSAGE layer  (256 threads: 2 node-halves x 128 dims)
//   agg = (x[n] + sum_s x[idx[n,s]]) / 17
//   h   = relu(agg @ w^T);  out = h / max(||h||, 1e-12)
// ---------------------------------------------------------------------------
__global__ __launch_bounds__(256) void layer_kernel(
    const float* __restrict__ xin,
    const int*   __restrict__ nidx,
    const float* __restrict__ w,
    float* __restrict__ xout)
{
    extern __shared__ float sm[];
    float* ws   = sm;                        // 128*132
    float* agg  = ws + DD * WPAD;            // 32*128 (reused as h after GEMM)
    float* invn = agg + NPB * DD;            // 32
    int*   idxs = (int*)(invn + NPB);        // 32*16  (16B-aligned)

    const int tid  = threadIdx.x;            // 0..255
    const int d    = tid & 127;              // output dim in GEMM phase
    const int half = tid >> 7;               // node half (0 or 1)
    const int base = blockIdx.x * NPB;

    // stage weights as float4 into padded rows (row stride 528B, 16B aligned)
    for (int q = tid; q < DD * DD / 4; q += 256) {
        float4 v = __ldg(((const float4*)w) + q);
        int dd = q >> 5, k = (q & 31) << 2;
        *(float4*)&ws[dd * WPAD + k] = v;
    }
    // stage neighbour indices (int4): 128 int4 total
    if (tid < NPB * SS / 4)
        ((int4*)idxs)[tid] = __ldg(((const int4*)(nidx + (size_t)base * SS)) + tid);
    __syncthreads();

    // ---- aggregation: 8 warps, each owns 4 nodes; lane owns one 16B chunk ----
    // Two independent FADD2 chains per chunk to halve the RAW dependency depth.
    {
        const int wrp  = tid >> 5;           // 0..7
        const int lane = tid & 31;
        const int coff = lane << 2;          // dim offset (4 floats)

#pragma unroll
        for (int k = 0; k < 4; k++) {
            const int node = wrp * 4 + k;
            const int4* ip = (const int4*)&idxs[node * SS];   // LDS.128 broadcast
            int4 q0 = ip[0], q1 = ip[1], q2 = ip[2], q3 = ip[3];
            int rows[16] = { q0.x, q0.y, q0.z, q0.w,
                             q1.x, q1.y, q1.z, q1.w,
                             q2.x, q2.y, q2.z, q2.w,
                             q3.x, q3.y, q3.z, q3.w };

            // chain A: self + neighbours 0..7 ; chain B: neighbours 8..15
            ulonglong2 accA = ldg128(&xin[(size_t)(base + node) * DD + coff]);
            ulonglong2 accB = ldg128(&xin[(size_t)rows[8] * DD + coff]);
#pragma unroll
            for (int j = 0; j < 8; j++) {
                ulonglong2 va = ldg128(&xin[(size_t)rows[j] * DD + coff]);   // LDG.128.CONSTANT
                fadd2(accA.x, va.x);
                fadd2(accA.y, va.y);
            }
#pragma unroll
            for (int j = 9; j < 16; j++) {
                ulonglong2 vb = ldg128(&xin[(size_t)rows[j] * DD + coff]);   // LDG.128.CONSTANT
                fadd2(accB.x, vb.x);
                fadd2(accB.y, vb.y);
            }
            fadd2(accA.x, accB.x);
            fadd2(accA.y, accB.y);

            float2 lo = up2(accA.x), hi = up2(accA.y);
            const float C = 1.0f / 17.0f;
            float4 r = { lo.x * C, lo.y * C, hi.x * C, hi.y * C };
            *(float4*)&agg[node * DD + coff] = r;              // STS.128 conflict-free
        }
    }
    __syncthreads();

    // ---- GEMM: h[half*16+i][d] = agg[...] . w[d]  (packed f32x2) ----
    unsigned long long acc2[NPT];
#pragma unroll
    for (int i = 0; i < NPT; i++) acc2[i] = 0ull;

    const float* aggh = agg + half * NPT * DD;
    const ulonglong2* wrow = (const ulonglong2*)&ws[d * WPAD];
#pragma unroll
    for (int k4 = 0; k4 < DD / 4; k4++) {
        ulonglong2 wv = wrow[k4];                              // LDS.128, conflict-free
#pragma unroll
        for (int i = 0; i < NPT; i++) {
            ulonglong2 av = *(const ulonglong2*)&aggh[i * DD + 4 * k4];  // LDS.128 broadcast
            ffma2(acc2[i], wv.x, av.x);
            ffma2(acc2[i], wv.y, av.y);
        }
    }
    __syncthreads();   // everyone done reading agg

    // ---- ReLU, stash h back into agg ----
#pragma unroll
    for (int i = 0; i < NPT; i++)
        agg[(half * NPT + i) * DD + d] = fmaxf(pair_hsum(acc2[i]), 0.0f);
    __syncthreads();

    // ---- L2 norm: 8 threads per node; node-rotated reads -> conflict-free ----
    {
        int node = tid >> 3, l8 = tid & 7;
        float sum = 0.0f;
#pragma unroll
        for (int j = 0; j < 16; j++) {
            int dim = (l8 + 8 * (j + node)) & 127;   // rotate start by node: distinct banks
            float v = agg[node * DD + dim];
            sum += v * v;
        }
        sum += __shfl_down_sync(0xffffffffu, sum, 4, 8);
        sum += __shfl_down_sync(0xffffffffu, sum, 2, 8);
        sum += __shfl_down_sync(0xffffffffu, sum, 1, 8);
        if (l8 == 0)
            invn[node] = 1.0f / fmaxf(sqrtf(sum), 1e-12f);
    }
    __syncthreads();

    // ---- normalized write-out: gather-layout vectorized (LDS.128 + STG.128) ----
    {
        const int wrp  = tid >> 5;           // 0..7
        const int lane = tid & 31;
        const int coff = lane << 2;
#pragma unroll
        for (int k = 0; k < 4; k++) {
            const int node = wrp * 4 + k;
            float4 v = *(const float4*)&agg[node * DD + coff];   // LDS.128 conflict-free
            float s = invn[node];                                // LDS broadcast
            float4 r = { v.x * s, v.y * s, v.z * s, v.w * s };
            *(float4*)&xout[(size_t)(base + node) * DD + coff] = r;   // STG.128 coalesced
        }
    }
}

// ---------------------------------------------------------------------------

static const int LAYER_SMEM = (DD * WPAD + NPB * DD + NPB) * 4 + NPB * SS * 4; // 86,144 B

extern "C" void kernel_launch(void* const* d_in, const int* in_sizes, int n_in,
                              void* d_out, int out_size)
{
    const float* feat  = (const float*)d_in[0];   // [N,64]
    const float* wfeat = (const float*)d_in[1];   // [128,64]
    const float* w1    = (const float*)d_in[2];   // [128,128]
    const float* w2    = (const float*)d_in[3];   // [128,128]
    const int*   n1    = (const int*)  d_in[4];   // [N,16]
    const int*   n2    = (const int*)  d_in[5];   // [N,16]
    float*       out   = (float*)d_out;           // [N,128]

    (void)in_sizes; (void)n_in; (void)out_size;

    void *p0, *p1;
    cudaGetSymbolAddress(&p0, g_x0);
    cudaGetSymbolAddress(&p1, g_x1);
    float* x0 = (float*)p0;
    float* x1 = (float*)p1;

    cudaFuncSetAttribute(layer_kernel,
                         cudaFuncAttributeMaxDynamicSharedMemorySize, LAYER_SMEM);

    const int blocks = NN / NPB;   // 3125

    feat_kernel<<<blocks, 256>>>(feat, wfeat, x0);
    layer_kernel<<<blocks, 256, LAYER_SMEM>>>(x0, n1, w1, x1);
    layer_kernel<<<blocks, 256, LAYER_SMEM>>>(x1, n2, w2, out);
}